// round 7
// baseline (speedup 1.0000x reference)
#include <cuda_runtime.h>
#include <math_constants.h>
#include <cstdint>

#define M_TOTAL 16384      // 4 * 4096 tokens
#define N_KEYS  4096
#define DHEAD   128
#define NQUAD   32         // 128 dims / 4 per dp4a word
#define HDIM    1024
#define TOPK    8
#define NCAND   16         // approx candidates -> exact fp32 rescue
#define EPS_F   1e-10f
#define SCALE_F 0.08838834764831845f   // 1/sqrt(128)

#define QSCALE  25.4f                  // 127 / 5.0
#define INV_S2  (1.0f / (QSCALE * QSCALE))

#define TM 128             // tokens per CTA
#define TN 128             // keys per tile
#define NTILES (N_KEYS / TN)   // 32

#define QW_STRIDE 33       // words per Q row  (32 quads + 1 pad)
#define KW_STRIDE 130      // words per K quad row (128 keys + 2 pad)
#define SB_STRIDE 132      // floats per score row

// ---------------- SMEM layout (bytes) ----------------
#define QS_OFF 0                        // u32 [128][33]  = 16896
#define KS_OFF 16896                    // u32 [32][130]  = 16640
#define SB_OFF 33536                    // f32 [128][132] = 67584
#define LR_OFF 101120                   // f32 [4096]     = 16384
#define SM_TOTAL 117504
// tail reuse:
#define MV_OFF 0                        // f32 [128][2][NCAND] = 16384
#define MI_OFF 16384                    // i32 [128][2][NCAND] = 16384
#define CAND_OFF SB_OFF                 // i32 [128][NCAND]    = 8192
#define EX_OFF  (SB_OFF + 8192)         // f32 [128][NCAND]    = 8192

// Scratch globals
__device__ uint32_t g_qi8[(size_t)M_TOTAL * NQUAD];    // [token][quad], 2 MB
__device__ uint32_t g_ki8t[(size_t)NQUAD * N_KEYS];    // [quad][key], 512 kB
__device__ float    g_logrel[N_KEYS];
__device__ float    g_w[M_TOTAL * TOPK];
__device__ int      g_idx[M_TOTAL * TOPK];

// ---------------------------------------------------------------------------
__device__ __forceinline__ uint32_t pack_i8(float4 v) {
    int a = __float2int_rn(fminf(fmaxf(v.x * QSCALE, -127.f), 127.f));
    int b = __float2int_rn(fminf(fmaxf(v.y * QSCALE, -127.f), 127.f));
    int c = __float2int_rn(fminf(fmaxf(v.z * QSCALE, -127.f), 127.f));
    int d = __float2int_rn(fminf(fmaxf(v.w * QSCALE, -127.f), 127.f));
    return (uint32_t)(a & 255) | ((uint32_t)(b & 255) << 8) |
           ((uint32_t)(c & 255) << 16) | ((uint32_t)(d & 255) << 24);
}
__device__ __forceinline__ int dp4a(int a, int b, int c) {
    int d;
    asm("dp4a.s32.s32 %0, %1, %2, %3;" : "=r"(d) : "r"(a), "r"(b), "r"(c));
    return d;
}

// ---------------------------------------------------------------------------
// Prep: quantize Q -> g_qi8[token][quad], K -> g_ki8t[quad][key], logrel.
// ---------------------------------------------------------------------------
#define QBLK ((M_TOTAL * NQUAD) / 256)          // 2048
#define KBLK ((N_KEYS * NQUAD) / 256)           // 512
__global__ void prep_kernel(const float* __restrict__ Q,
                            const float* __restrict__ K,
                            const float* __restrict__ rel) {
    int b = blockIdx.x, t = threadIdx.x;
    if (b < QBLK) {
        int i = b * 256 + t;                    // quad-flat: token*32+quad
        float4 v = *(const float4*)(Q + (size_t)i * 4);
        g_qi8[i] = pack_i8(v);
    } else if (b < QBLK + KBLK) {
        int j = (b - QBLK) * 256 + t;           // quad*4096 + key
        int quad = j >> 12, key = j & (N_KEYS - 1);
        float4 v = *(const float4*)(K + (size_t)key * DHEAD + quad * 4);
        g_ki8t[j] = pack_i8(v);
    } else {
        int j = (b - QBLK - KBLK) * 256 + t;
        if (j < N_KEYS) g_logrel[j] = logf(rel[j] + EPS_F);
    }
}

// ---------------------------------------------------------------------------
// Fused: int8 dp4a approx scores + online top-16 + exact fp32 rescue + softmax.
// 256 threads; tx = tid&15 (key group), ty = tid>>4 (token group).
// Micro-tile 8 tokens x 4 keys; two 64-key half-passes per 128-key tile.
// ---------------------------------------------------------------------------
__global__ __launch_bounds__(256, 1)
void fused_dp4a(const float* __restrict__ Q, const float* __restrict__ K,
                float* __restrict__ w_out) {
    extern __shared__ char smem[];
    uint32_t* Qs  = (uint32_t*)(smem + QS_OFF);
    uint32_t* Ks  = (uint32_t*)(smem + KS_OFF);
    float*    Sb  = (float*)(smem + SB_OFF);
    float*    lrS = (float*)(smem + LR_OFF);

    const int tid = threadIdx.x;
    const int tx  = tid & 15;
    const int ty  = tid >> 4;
    const int m0  = blockIdx.x * TM;

    // logrel -> smem
    #pragma unroll
    for (int i = tid; i < N_KEYS; i += 256) lrS[i] = g_logrel[i];

    // quantized Q tile -> smem (coalesced read, conflict-free write)
    #pragma unroll
    for (int i = 0; i < 16; ++i) {
        int idx = tid + i * 256;                // token*32 + quad
        int r = idx >> 5, qd = idx & 31;
        Qs[r * QW_STRIDE + qd] = g_qi8[(size_t)(m0 + r) * NQUAD + idx - r * 32];
        (void)qd;
    }

    // running top-16 per (token, key-half): strict > keeps first occurrence
    float lv[NCAND];
    int   li[NCAND];
    #pragma unroll
    for (int k = 0; k < NCAND; ++k) { lv[k] = -CUDART_INF_F; li[k] = 0x7fffffff; }
    const int tok = tid >> 1;
    const int hlf = tid & 1;

    for (int t = 0; t < NTILES; ++t) {
        __syncthreads();   // scan of t-1 done before Ks rewrite

        // K tile: quad rows, keys [t*128, t*128+128); coalesced read,
        // conflict-free write (consecutive tid -> consecutive key)
        #pragma unroll
        for (int i = 0; i < 16; ++i) {
            int idx = tid + i * 256;            // quad*128 + key
            int qd = idx >> 7, kc = idx & 127;
            Ks[qd * KW_STRIDE + kc] = g_ki8t[(size_t)qd * N_KEYS + t * TN + kc];
        }
        __syncthreads();

        // two 64-key half passes (acc = 32 int regs)
        #pragma unroll
        for (int hp = 0; hp < 2; ++hp) {
            int acc[8][4];
            #pragma unroll
            for (int i = 0; i < 8; ++i)
                #pragma unroll
                for (int j = 0; j < 4; ++j) acc[i][j] = 0;

            const uint32_t* KsH = Ks + hp * 64 + tx;
            #pragma unroll 8
            for (int qd = 0; qd < NQUAD; ++qd) {
                int kk[4];
                #pragma unroll
                for (int j = 0; j < 4; ++j)
                    kk[j] = (int)KsH[qd * KW_STRIDE + 16 * j];
                #pragma unroll
                for (int i = 0; i < 8; ++i) {
                    int qq = (int)Qs[(ty + 16 * i) * QW_STRIDE + qd];
                    #pragma unroll
                    for (int j = 0; j < 4; ++j)
                        acc[i][j] = dp4a(qq, kk[j], acc[i][j]);
                }
            }

            // approx biased scores -> Sb
            float lr[4];
            #pragma unroll
            for (int j = 0; j < 4; ++j)
                lr[j] = lrS[t * TN + hp * 64 + 16 * j + tx];
            #pragma unroll
            for (int i = 0; i < 8; ++i) {
                float* row = Sb + (ty + 16 * i) * SB_STRIDE + hp * 64 + tx;
                #pragma unroll
                for (int j = 0; j < 4; ++j)
                    row[16 * j] = (float)acc[i][j] * INV_S2 + lr[j];
            }
        }
        __syncthreads();   // Sb(t) complete

        // scan: 2 threads per token, 64 keys each (float4 reads)
        const int nb = t * TN + hlf * 64;
        const float* srow = Sb + tok * SB_STRIDE + hlf * 64;
        #pragma unroll
        for (int c4 = 0; c4 < 16; ++c4) {
            float4 sv = *(const float4*)(srow + 4 * c4);
            float vs[4] = {sv.x, sv.y, sv.z, sv.w};
            #pragma unroll
            for (int e = 0; e < 4; ++e) {
                float v = vs[e];
                if (v > lv[NCAND - 1]) {
                    lv[NCAND - 1] = v; li[NCAND - 1] = nb + 4 * c4 + e;
                    #pragma unroll
                    for (int s = NCAND - 1; s > 0; --s) {
                        if (lv[s] > lv[s - 1]) {
                            float tv = lv[s]; lv[s] = lv[s-1]; lv[s-1] = tv;
                            int   ti = li[s]; li[s] = li[s-1]; li[s-1] = ti;
                        } else break;
                    }
                }
            }
        }
    }
    __syncthreads();   // all scans done; Qs/Ks regions reusable

    // dump per-half candidate lists
    float* mval = (float*)(smem + MV_OFF);
    int*   midx = (int*)(smem + MI_OFF);
    #pragma unroll
    for (int k = 0; k < NCAND; ++k) {
        mval[(tok * 2 + hlf) * NCAND + k] = lv[k];
        midx[(tok * 2 + hlf) * NCAND + k] = li[k];
    }
    __syncthreads();

    // stable merge of two sorted 16-lists -> approx top-16 candidate indices
    int*   candIdx = (int*)(smem + CAND_OFF);
    float* exactS  = (float*)(smem + EX_OFF);
    if (tid < TM) {
        const float* va = mval + (tid * 2 + 0) * NCAND;
        const float* vb = mval + (tid * 2 + 1) * NCAND;
        const int*   xa = midx + (tid * 2 + 0) * NCAND;
        const int*   xb = midx + (tid * 2 + 1) * NCAND;
        int ia = 0, ib = 0;
        #pragma unroll
        for (int k = 0; k < NCAND; ++k) {
            float A = va[ia], B = vb[ib];
            bool takeA = (A > B) || (A == B && xa[ia] < xb[ib]);
            candIdx[tid * NCAND + k] = takeA ? xa[ia] : xb[ib];
            if (takeA) ++ia; else ++ib;
        }
    }
    __syncthreads();

    // exact fp32 serial rescore of 128*16 candidates (8 per thread)
    #pragma unroll
    for (int p = tid; p < TM * NCAND; p += 256) {
        const int tk  = p / NCAND;
        const int idx = candIdx[p];
        const float* qrow = Q + (size_t)(m0 + tk) * DHEAD;
        const float* krow = K + (size_t)idx * DHEAD;
        float dot = 0.0f;
        #pragma unroll
        for (int d4 = 0; d4 < DHEAD / 4; ++d4) {
            float4 qv = *(const float4*)(qrow + 4 * d4);
            float4 kv = *(const float4*)(krow + 4 * d4);
            dot = fmaf(qv.x, kv.x, dot);
            dot = fmaf(qv.y, kv.y, dot);
            dot = fmaf(qv.z, kv.z, dot);
            dot = fmaf(qv.w, kv.w, dot);
        }
        exactS[p] = dot + lrS[idx];
    }
    __syncthreads();

    // exact top-8 (desc, index-asc ties), softmax, store
    if (tid < TM) {
        float cv[NCAND]; int ci[NCAND];
        #pragma unroll
        for (int k = 0; k < NCAND; ++k) {
            cv[k] = exactS[tid * NCAND + k];
            ci[k] = candIdx[tid * NCAND + k];
        }
        float fv[TOPK]; int fi[TOPK];
        #pragma unroll
        for (int k = 0; k < TOPK; ++k) {
            int best = 0;
            #pragma unroll
            for (int c = 1; c < NCAND; ++c) {
                bool better = (cv[c] > cv[best]) ||
                              (cv[c] == cv[best] && ci[c] < ci[best]);
                if (better) best = c;
            }
            fv[k] = cv[best]; fi[k] = ci[best];
            cv[best] = -CUDART_INF_F; ci[best] = 0x7fffffff;
        }
        float sc[TOPK], mx = -CUDART_INF_F;
        #pragma unroll
        for (int k = 0; k < TOPK; ++k) {
            sc[k] = (fv[k] - lrS[fi[k]]) * SCALE_F;
            mx = fmaxf(mx, sc[k]);
        }
        float sum = 0.0f;
        #pragma unroll
        for (int k = 0; k < TOPK; ++k) { sc[k] = expf(sc[k] - mx); sum += sc[k]; }
        float inv = 1.0f / sum;
        const int token = m0 + tid;
        #pragma unroll
        for (int k = 0; k < TOPK; ++k) {
            float w = sc[k] * inv;
            w_out[(size_t)token * TOPK + k] = w;
            g_w[token * TOPK + k]   = w;
            g_idx[token * TOPK + k] = fi[k];
        }
    }
}

// ---------------------------------------------------------------------------
// Gather: out[token][h] = sum_k w_k * values[idx_k][h]
// ---------------------------------------------------------------------------
__global__ __launch_bounds__(256)
void gather_kernel(const float* __restrict__ values, float* __restrict__ out) {
    const int token = blockIdx.x;
    const int h = threadIdx.x << 2;

    __shared__ float ws[TOPK];
    __shared__ int   is[TOPK];
    if (threadIdx.x < TOPK) {
        ws[threadIdx.x] = g_w[token * TOPK + threadIdx.x];
        is[threadIdx.x] = g_idx[token * TOPK + threadIdx.x];
    }
    __syncthreads();

    float4 acc = make_float4(0.f, 0.f, 0.f, 0.f);
    #pragma unroll
    for (int k = 0; k < TOPK; ++k) {
        float w = ws[k];
        const float4 v = *(const float4*)(values + (size_t)is[k] * HDIM + h);
        acc.x = fmaf(w, v.x, acc.x);
        acc.y = fmaf(w, v.y, acc.y);
        acc.z = fmaf(w, v.z, acc.z);
        acc.w = fmaf(w, v.w, acc.w);
    }
    *(float4*)(out + (size_t)token * HDIM + h) = acc;
}

// ---------------------------------------------------------------------------
extern "C" void kernel_launch(void* const* d_in, const int* in_sizes, int n_in,
                              void* d_out, int out_size) {
    const float* query = (const float*)d_in[0];   // [4,4096,128]
    const float* keys  = (const float*)d_in[1];   // [4096,128]
    const float* vals  = (const float*)d_in[2];   // [4096,1024]
    const float* rel   = (const float*)d_in[3];   // [4096]

    float* out   = (float*)d_out;                        // [4,4096,1024]
    float* w_out = out + (size_t)M_TOTAL * HDIM;         // [4,4096,8]

    cudaFuncSetAttribute(fused_dp4a,
                         cudaFuncAttributeMaxDynamicSharedMemorySize, SM_TOTAL);

    prep_kernel<<<QBLK + KBLK + (N_KEYS + 255) / 256, 256>>>(query, keys, rel);
    fused_dp4a<<<M_TOTAL / TM, 256, SM_TOTAL>>>(query, keys, w_out);
    gather_kernel<<<M_TOTAL, 256>>>(vals, out);
}